// round 3
// baseline (speedup 1.0000x reference)
#include <cuda_runtime.h>

#define D 64
#define MAXN 100000
#define MAXE 1600000
#define TILE 128
#define RSTRIDE 68   // padded row stride (floats) for node-major smem arrays

typedef unsigned long long u64;

// ---------------- static scratch (no allocation allowed) -------------------
__device__ float g_h[(size_t)MAXN * D];
__device__ int   g_deg[MAXN];
__device__ int   g_rowptr[MAXN];
__device__ int   g_cursor[MAXN];
__device__ int   g_csrsrc[MAXE];
__device__ int   g_blocksums[128];
__device__ int   g_blockoffs[128];

// ---------------- f32x2 helpers --------------------------------------------
__device__ __forceinline__ u64 fma2(u64 a, u64 b, u64 c) {
    u64 d;
    asm("fma.rn.f32x2 %0, %1, %2, %3;" : "=l"(d) : "l"(a), "l"(b), "l"(c));
    return d;
}
__device__ __forceinline__ u64 pack2(float v) {
    u64 d;
    asm("mov.b64 %0, {%1, %1};" : "=l"(d) : "f"(v));
    return d;
}
__device__ __forceinline__ void unpack2(u64 v, float& lo, float& hi) {
    asm("mov.b64 {%0, %1}, %2;" : "=f"(lo), "=f"(hi) : "l"(v));
}

// ---------------- CSR build ------------------------------------------------
__global__ void count_kernel(const int* __restrict__ dst, int* __restrict__ deg,
                             int n_edges) {
    int e = blockIdx.x * blockDim.x + threadIdx.x;
    if (e < n_edges) atomicAdd(deg + __ldg(dst + e), 1);
}

__global__ void scan_kernel(const int* __restrict__ in, int* __restrict__ out,
                            int* sums, int n) {
    __shared__ int sm[1024];
    int t = threadIdx.x;
    int i = blockIdx.x * 1024 + t;
    int v = (i < n) ? in[i] : 0;
    sm[t] = v;
    __syncthreads();
#pragma unroll
    for (int off = 1; off < 1024; off <<= 1) {
        int add = (t >= off) ? sm[t - off] : 0;
        __syncthreads();
        sm[t] += add;
        __syncthreads();
    }
    if (i < n) out[i] = sm[t] - v;            // exclusive
    if (sums != nullptr && t == 1023) sums[blockIdx.x] = sm[1023];
}

__global__ void add_off_kernel(int* __restrict__ rowptr, int* __restrict__ cursor,
                               const int* __restrict__ boffs, int n) {
    int i = blockIdx.x * blockDim.x + threadIdx.x;
    if (i < n) {
        int v = rowptr[i] + boffs[i >> 10];
        rowptr[i] = v;
        cursor[i] = v;
    }
}

__global__ void fill_kernel(const int* __restrict__ src, const int* __restrict__ dst,
                            int* __restrict__ cursor, int* __restrict__ csr,
                            int n_edges) {
    int e = blockIdx.x * blockDim.x + threadIdx.x;
    if (e < n_edges) {
        int d = __ldg(dst + e);
        int pos = atomicAdd(cursor + d, 1);
        csr[pos] = __ldg(src + e);
    }
}

// ---------------------------------------------------------------------------
// Fused layer: per block of 128 nodes,
//   phase 1: warp-per-node CSR gather -> mean + x staged node-major in SMEM
//   phase 2: out = mean@Wl^T + b + x@Wr^T (+ReLU), feature-packed f32x2
// ---------------------------------------------------------------------------
__global__ void __launch_bounds__(256, 2)
fused_layer_kernel(const float2* __restrict__ x2,
                   const int* __restrict__ csr,
                   const int* __restrict__ rowptr,
                   const int* __restrict__ deg,
                   const float* __restrict__ Wl,
                   const float* __restrict__ bl,
                   const float* __restrict__ Wr,
                   float* __restrict__ out,
                   int n_nodes, int do_relu) {
    extern __shared__ float sm[];
    float* wlT = sm;                       // [64][64]  wlT[k*64+f] = Wl[f][k]
    float* wrT = wlT + D * D;              // [64][64]
    float* msE = wrT + D * D;              // [64][RSTRIDE] even nodes (node-major)
    float* msO = msE + 64 * RSTRIDE;       // odd nodes
    float* xsE = msO + 64 * RSTRIDE;
    float* xsO = xsE + 64 * RSTRIDE;

    int tid = threadIdx.x;

    // stage transposed weights
    for (int i = tid; i < D * D; i += 256) {
        int f = i >> 6, k = i & 63;
        wlT[k * D + f] = Wl[i];
        wrT[k * D + f] = Wr[i];
    }

    int nb = blockIdx.x * TILE;
    int warp = tid >> 5, lane = tid & 31;

    // ---- phase 1: gather-aggregate + stage self features ----
    for (int i = warp; i < TILE; i += 8) {
        int gn = nb + i;
        if (gn >= n_nodes) break;
        float2 xv = __ldg(x2 + (size_t)gn * 32 + lane);
        int base = __ldg(rowptr + gn);
        int dg = __ldg(deg + gn);

        float2 a0 = {0.f, 0.f}, a1 = {0.f, 0.f}, a2 = {0.f, 0.f}, a3 = {0.f, 0.f};
        int j = 0;
        for (; j + 4 <= dg; j += 4) {
            int s0 = __ldg(csr + base + j);
            int s1 = __ldg(csr + base + j + 1);
            int s2 = __ldg(csr + base + j + 2);
            int s3 = __ldg(csr + base + j + 3);
            float2 v0 = __ldg(x2 + (size_t)s0 * 32 + lane);
            float2 v1 = __ldg(x2 + (size_t)s1 * 32 + lane);
            float2 v2 = __ldg(x2 + (size_t)s2 * 32 + lane);
            float2 v3 = __ldg(x2 + (size_t)s3 * 32 + lane);
            a0.x += v0.x; a0.y += v0.y;
            a1.x += v1.x; a1.y += v1.y;
            a2.x += v2.x; a2.y += v2.y;
            a3.x += v3.x; a3.y += v3.y;
        }
        for (; j < dg; j++) {
            int s = __ldg(csr + base + j);
            float2 v = __ldg(x2 + (size_t)s * 32 + lane);
            a0.x += v.x; a0.y += v.y;
        }
        float ax = (a0.x + a1.x) + (a2.x + a3.x);
        float ay = (a0.y + a1.y) + (a2.y + a3.y);
        float inv = 1.0f / fmaxf((float)dg, 1.0f);

        float* mr = ((i & 1) ? msO : msE) + (i >> 1) * RSTRIDE;
        float* xr = ((i & 1) ? xsO : xsE) + (i >> 1) * RSTRIDE;
        ((float2*)mr)[lane] = make_float2(ax * inv, ay * inv);
        ((float2*)xr)[lane] = xv;
    }
    __syncthreads();

    // ---- phase 2: GEMM-combine ----
    // thread: fq = tid&3 (16 features = 8 feature-pairs), p = tid>>2 (node pair 2p, 2p+1)
    int fq = tid & 3;
    int p = tid >> 2;

    u64 accE[8], accO[8];
    const u64* bl8 = (const u64*)bl;       // feature pairs straight from bias
#pragma unroll
    for (int j2 = 0; j2 < 8; j2++) {
        u64 b = __ldg(bl8 + fq * 8 + j2);
        accE[j2] = b;
        accO[j2] = b;
    }

#pragma unroll 2
    for (int k4 = 0; k4 < D; k4 += 4) {
        float4 mE = *(const float4*)(msE + p * RSTRIDE + k4);
        float4 mO = *(const float4*)(msO + p * RSTRIDE + k4);
        float4 xE = *(const float4*)(xsE + p * RSTRIDE + k4);
        float4 xO = *(const float4*)(xsO + p * RSTRIDE + k4);
        float mEa[4] = {mE.x, mE.y, mE.z, mE.w};
        float mOa[4] = {mO.x, mO.y, mO.z, mO.w};
        float xEa[4] = {xE.x, xE.y, xE.z, xE.w};
        float xOa[4] = {xO.x, xO.y, xO.z, xO.w};
#pragma unroll
        for (int kk = 0; kk < 4; kk++) {
            int k = k4 + kk;
            u64 pmE = pack2(mEa[kk]);
            u64 pmO = pack2(mOa[kk]);
            u64 pxE = pack2(xEa[kk]);
            u64 pxO = pack2(xOa[kk]);
            const ulonglong2* wlr = (const ulonglong2*)(wlT + k * D + fq * 16);
            const ulonglong2* wrr = (const ulonglong2*)(wrT + k * D + fq * 16);
            ulonglong2 wl01 = wlr[0], wl23 = wlr[1], wl45 = wlr[2], wl67 = wlr[3];
            ulonglong2 wr01 = wrr[0], wr23 = wrr[1], wr45 = wrr[2], wr67 = wrr[3];
            u64 wlv[8] = {wl01.x, wl01.y, wl23.x, wl23.y, wl45.x, wl45.y, wl67.x, wl67.y};
            u64 wrv[8] = {wr01.x, wr01.y, wr23.x, wr23.y, wr45.x, wr45.y, wr67.x, wr67.y};
#pragma unroll
            for (int j2 = 0; j2 < 8; j2++) {
                accE[j2] = fma2(pmE, wlv[j2], accE[j2]);
                accE[j2] = fma2(pxE, wrv[j2], accE[j2]);
                accO[j2] = fma2(pmO, wlv[j2], accO[j2]);
                accO[j2] = fma2(pxO, wrv[j2], accO[j2]);
            }
        }
    }

    // ---- epilogue ----
    int gnE = nb + 2 * p;
    int gnO = gnE + 1;
#pragma unroll
    for (int q = 0; q < 4; q++) {          // 4 float4 stores per node
        float e0, e1, e2, e3, o0, o1, o2, o3;
        unpack2(accE[2 * q + 0], e0, e1);
        unpack2(accE[2 * q + 1], e2, e3);
        unpack2(accO[2 * q + 0], o0, o1);
        unpack2(accO[2 * q + 1], o2, o3);
        if (do_relu) {
            e0 = fmaxf(e0, 0.f); e1 = fmaxf(e1, 0.f);
            e2 = fmaxf(e2, 0.f); e3 = fmaxf(e3, 0.f);
            o0 = fmaxf(o0, 0.f); o1 = fmaxf(o1, 0.f);
            o2 = fmaxf(o2, 0.f); o3 = fmaxf(o3, 0.f);
        }
        if (gnE < n_nodes)
            *(float4*)(out + (size_t)gnE * D + fq * 16 + 4 * q) =
                make_float4(e0, e1, e2, e3);
        if (gnO < n_nodes)
            *(float4*)(out + (size_t)gnO * D + fq * 16 + 4 * q) =
                make_float4(o0, o1, o2, o3);
    }
}

// ---------------------------------------------------------------------------
extern "C" void kernel_launch(void* const* d_in, const int* in_sizes, int n_in,
                              void* d_out, int out_size) {
    const float* x   = (const float*)d_in[0];
    const int*   ei  = (const int*)  d_in[1];
    const float* W1l = (const float*)d_in[2];
    const float* b1l = (const float*)d_in[3];
    const float* W1r = (const float*)d_in[4];
    const float* W2l = (const float*)d_in[5];
    const float* b2l = (const float*)d_in[6];
    const float* W2r = (const float*)d_in[7];
    float* out = (float*)d_out;

    int n_nodes = in_sizes[0] / D;
    int n_edges = in_sizes[1] / 2;
    const int* src = ei;
    const int* dst = ei + n_edges;

    float *h;
    int *deg, *rowptr, *cursor, *csr, *bsums, *boffs;
    cudaGetSymbolAddress((void**)&h,      g_h);
    cudaGetSymbolAddress((void**)&deg,    g_deg);
    cudaGetSymbolAddress((void**)&rowptr, g_rowptr);
    cudaGetSymbolAddress((void**)&cursor, g_cursor);
    cudaGetSymbolAddress((void**)&csr,    g_csrsrc);
    cudaGetSymbolAddress((void**)&bsums,  g_blocksums);
    cudaGetSymbolAddress((void**)&boffs,  g_blockoffs);

    const int SMEM = (2 * D * D + 4 * 64 * RSTRIDE) * (int)sizeof(float); // 100.6 KB
    cudaFuncSetAttribute(fused_layer_kernel,
                         cudaFuncAttributeMaxDynamicSharedMemorySize, SMEM);

    int eblocks = (n_edges + 255) / 256;
    int nscan = (n_nodes + 1023) / 1024;
    int nblocks = (n_nodes + 255) / 256;
    int fblocks = (n_nodes + TILE - 1) / TILE;

    // ---- CSR build (once per call) ----
    cudaMemsetAsync(deg, 0, (size_t)n_nodes * sizeof(int));
    count_kernel<<<eblocks, 256>>>(dst, deg, n_edges);
    scan_kernel<<<nscan, 1024>>>(deg, rowptr, bsums, n_nodes);
    scan_kernel<<<1, 1024>>>(bsums, boffs, nullptr, nscan);
    add_off_kernel<<<nblocks, 256>>>(rowptr, cursor, boffs, n_nodes);
    fill_kernel<<<eblocks, 256>>>(src, dst, cursor, csr, n_edges);

    // ---- Layer 1 (fused aggregate + combine + ReLU) ----
    fused_layer_kernel<<<fblocks, 256, SMEM>>>((const float2*)x, csr, rowptr,
                                               deg, W1l, b1l, W1r, h,
                                               n_nodes, 1);
    // ---- Layer 2 ----
    fused_layer_kernel<<<fblocks, 256, SMEM>>>((const float2*)h, csr, rowptr,
                                               deg, W2l, b2l, W2r, out,
                                               n_nodes, 0);
}

// round 4
// speedup vs baseline: 1.5556x; 1.5556x over previous
#include <cuda_runtime.h>

#define D 64
#define MAXN 100000
#define MAXE 1600000
#define TILE 128
#define RS 132          // padded k-row stride (floats) in combine smem
#define RS64 66         // same, in u64 units

typedef unsigned long long u64;

// ---------------- static scratch (no allocation allowed) -------------------
__device__ float g_mean[(size_t)MAXN * D];
__device__ float g_h[(size_t)MAXN * D];
__device__ int   g_deg[MAXN];
__device__ int   g_rowptr[MAXN];
__device__ int   g_cursor[MAXN];
__device__ int   g_csrsrc[MAXE];
__device__ int   g_blocksums[128];
__device__ int   g_blockoffs[128];

// ---------------- f32x2 helpers --------------------------------------------
__device__ __forceinline__ u64 fma2(u64 a, u64 b, u64 c) {
    u64 d;
    asm("fma.rn.f32x2 %0, %1, %2, %3;" : "=l"(d) : "l"(a), "l"(b), "l"(c));
    return d;
}
__device__ __forceinline__ u64 pack2(float v) {
    u64 d;
    asm("mov.b64 %0, {%1, %1};" : "=l"(d) : "f"(v));
    return d;
}
__device__ __forceinline__ void unpack2(u64 v, float& lo, float& hi) {
    asm("mov.b64 {%0, %1}, %2;" : "=f"(lo), "=f"(hi) : "l"(v));
}

// ---------------- CSR build ------------------------------------------------
__global__ void count_kernel(const int* __restrict__ dst, int* __restrict__ deg,
                             int n_edges) {
    int e = blockIdx.x * blockDim.x + threadIdx.x;
    if (e < n_edges) atomicAdd(deg + __ldg(dst + e), 1);
}

__global__ void scan_kernel(const int* __restrict__ in, int* __restrict__ out,
                            int* sums, int n) {
    __shared__ int sm[1024];
    int t = threadIdx.x;
    int i = blockIdx.x * 1024 + t;
    int v = (i < n) ? in[i] : 0;
    sm[t] = v;
    __syncthreads();
#pragma unroll
    for (int off = 1; off < 1024; off <<= 1) {
        int add = (t >= off) ? sm[t - off] : 0;
        __syncthreads();
        sm[t] += add;
        __syncthreads();
    }
    if (i < n) out[i] = sm[t] - v;            // exclusive
    if (sums != nullptr && t == 1023) sums[blockIdx.x] = sm[1023];
}

__global__ void add_off_kernel(int* __restrict__ rowptr, int* __restrict__ cursor,
                               const int* __restrict__ boffs, int n) {
    int i = blockIdx.x * blockDim.x + threadIdx.x;
    if (i < n) {
        int v = rowptr[i] + boffs[i >> 10];
        rowptr[i] = v;
        cursor[i] = v;
    }
}

__global__ void fill_kernel(const int* __restrict__ src, const int* __restrict__ dst,
                            int* __restrict__ cursor, int* __restrict__ csr,
                            int n_edges) {
    int e = blockIdx.x * blockDim.x + threadIdx.x;
    if (e < n_edges) {
        int d = __ldg(dst + e);
        int pos = atomicAdd(cursor + d, 1);
        csr[pos] = __ldg(src + e);
    }
}

// ---------------- aggregate: mean of in-neighbors (warp per node) ----------
__global__ void aggregate_kernel(const float2* __restrict__ x2,
                                 const int* __restrict__ csr,
                                 const int* __restrict__ rowptr,
                                 const int* __restrict__ deg,
                                 float2* __restrict__ mean2, int n_nodes) {
    int warp = (blockIdx.x * blockDim.x + threadIdx.x) >> 5;
    if (warp >= n_nodes) return;
    int lane = threadIdx.x & 31;
    int base = __ldg(rowptr + warp);
    int dg = __ldg(deg + warp);

    float2 a0 = {0.f, 0.f}, a1 = {0.f, 0.f}, a2 = {0.f, 0.f}, a3 = {0.f, 0.f};
    int j = 0;
    for (; j + 4 <= dg; j += 4) {
        int s0 = __ldg(csr + base + j);
        int s1 = __ldg(csr + base + j + 1);
        int s2 = __ldg(csr + base + j + 2);
        int s3 = __ldg(csr + base + j + 3);
        float2 v0 = __ldg(x2 + (size_t)s0 * 32 + lane);
        float2 v1 = __ldg(x2 + (size_t)s1 * 32 + lane);
        float2 v2 = __ldg(x2 + (size_t)s2 * 32 + lane);
        float2 v3 = __ldg(x2 + (size_t)s3 * 32 + lane);
        a0.x += v0.x; a0.y += v0.y;
        a1.x += v1.x; a1.y += v1.y;
        a2.x += v2.x; a2.y += v2.y;
        a3.x += v3.x; a3.y += v3.y;
    }
    for (; j < dg; j++) {
        int s = __ldg(csr + base + j);
        float2 v = __ldg(x2 + (size_t)s * 32 + lane);
        a0.x += v.x; a0.y += v.y;
    }
    float2 a;
    a.x = (a0.x + a1.x) + (a2.x + a3.x);
    a.y = (a0.y + a1.y) + (a2.y + a3.y);
    float inv = 1.0f / fmaxf((float)dg, 1.0f);
    a.x *= inv; a.y *= inv;
    mean2[(size_t)warp * 32 + lane] = a;
}

// ---------------- combine: out = mean@Wl^T + b + x@Wr^T (+ReLU) ------------
// 128 threads, TILE=128 nodes/block, 16 nodes x 4 features per thread.
// Node data staged k-major (stride RS); node-axis f32x2 packing.
__global__ void __launch_bounds__(128, 2)
combine_kernel(const float* __restrict__ xin,
               const float* __restrict__ mean,
               const float* __restrict__ Wl,
               const float* __restrict__ bl,
               const float* __restrict__ Wr,
               float* __restrict__ out,
               int n_nodes, int do_relu) {
    extern __shared__ float sm[];
    float* wlT = sm;                 // [64][64]  wlT[k*64+f] = Wl[f][k]
    float* wrT = wlT + D * D;        // [64][64]
    float* msT = wrT + D * D;        // [64][RS]  k-major, nodes 0..127
    float* xsT = msT + D * RS;       // [64][RS]

    int tid = threadIdx.x;

    // stage transposed weights (4096 each, 32 iters)
    for (int i = tid; i < D * D; i += 128) {
        int f = i >> 6, k = i & 63;
        wlT[k * D + f] = Wl[i];
        wrT[k * D + f] = Wr[i];
    }

    int nb = blockIdx.x * TILE;
    int kq = tid & 15;               // k-quad within a row sweep
    int ng = tid >> 4;               // node sub-index, 0..7

    // stage node data: 16 iterations x 8 nodes; 16 lanes sweep one 256B row
    for (int it = 0; it < 16; it++) {
        int n = it * 8 + ng;
        int gn = nb + n;
        int k4 = kq * 4;
        float4 xv = make_float4(0.f, 0.f, 0.f, 0.f);
        float4 mv = make_float4(0.f, 0.f, 0.f, 0.f);
        if (gn < n_nodes) {
            xv = __ldg((const float4*)(xin + (size_t)gn * D + k4));
            mv = __ldg((const float4*)(mean + (size_t)gn * D + k4));
        }
        xsT[(k4 + 0) * RS + n] = xv.x;
        xsT[(k4 + 1) * RS + n] = xv.y;
        xsT[(k4 + 2) * RS + n] = xv.z;
        xsT[(k4 + 3) * RS + n] = xv.w;
        msT[(k4 + 0) * RS + n] = mv.x;
        msT[(k4 + 1) * RS + n] = mv.y;
        msT[(k4 + 2) * RS + n] = mv.z;
        msT[(k4 + 3) * RS + n] = mv.w;
    }
    __syncthreads();

    // ---- GEMM phase ----
    int fq = tid & 15;               // feature quad: features 4*fq..4*fq+3
    int g  = tid >> 4;               // pair group: pairs g, g+8, ..., g+56

    float4 b4 = __ldg((const float4*)(bl + fq * 4));
    u64 bp[4] = {pack2(b4.x), pack2(b4.y), pack2(b4.z), pack2(b4.w)};
    u64 acc[8][4];
#pragma unroll
    for (int j = 0; j < 8; j++) {
        acc[j][0] = bp[0]; acc[j][1] = bp[1];
        acc[j][2] = bp[2]; acc[j][3] = bp[3];
    }

    const float4* wl4 = (const float4*)wlT;
    const float4* wr4 = (const float4*)wrT;
    const u64* msv = (const u64*)msT;    // RS64 u64 per k-row
    const u64* xsv = (const u64*)xsT;

#pragma unroll 2
    for (int k = 0; k < D; k++) {
        float4 wl = wl4[k * 16 + fq];
        float4 wr = wr4[k * 16 + fq];
        u64 wl2[4] = {pack2(wl.x), pack2(wl.y), pack2(wl.z), pack2(wl.w)};
        u64 wr2[4] = {pack2(wr.x), pack2(wr.y), pack2(wr.z), pack2(wr.w)};
        u64 m[8], x[8];
#pragma unroll
        for (int j = 0; j < 8; j++) {
            int p = g + 8 * j;               // node pair index (nodes 2p, 2p+1)
            m[j] = msv[k * RS64 + p];
            x[j] = xsv[k * RS64 + p];
        }
#pragma unroll
        for (int j = 0; j < 8; j++) {
#pragma unroll
            for (int f = 0; f < 4; f++) {
                acc[j][f] = fma2(m[j], wl2[f], acc[j][f]);
                acc[j][f] = fma2(x[j], wr2[f], acc[j][f]);
            }
        }
    }

    // ---- epilogue: pair j -> nodes 2(g+8j), 2(g+8j)+1 ----
#pragma unroll
    for (int j = 0; j < 8; j++) {
        int p = g + 8 * j;
        int gn0 = nb + 2 * p;
        int gn1 = gn0 + 1;
        float lo[4], hi[4];
#pragma unroll
        for (int f = 0; f < 4; f++) unpack2(acc[j][f], lo[f], hi[f]);
        if (do_relu) {
#pragma unroll
            for (int f = 0; f < 4; f++) {
                lo[f] = fmaxf(lo[f], 0.f);
                hi[f] = fmaxf(hi[f], 0.f);
            }
        }
        if (gn0 < n_nodes)
            *(float4*)(out + (size_t)gn0 * D + fq * 4) =
                make_float4(lo[0], lo[1], lo[2], lo[3]);
        if (gn1 < n_nodes)
            *(float4*)(out + (size_t)gn1 * D + fq * 4) =
                make_float4(hi[0], hi[1], hi[2], hi[3]);
    }
}

// ---------------------------------------------------------------------------
extern "C" void kernel_launch(void* const* d_in, const int* in_sizes, int n_in,
                              void* d_out, int out_size) {
    const float* x   = (const float*)d_in[0];
    const int*   ei  = (const int*)  d_in[1];
    const float* W1l = (const float*)d_in[2];
    const float* b1l = (const float*)d_in[3];
    const float* W1r = (const float*)d_in[4];
    const float* W2l = (const float*)d_in[5];
    const float* b2l = (const float*)d_in[6];
    const float* W2r = (const float*)d_in[7];
    float* out = (float*)d_out;

    int n_nodes = in_sizes[0] / D;
    int n_edges = in_sizes[1] / 2;
    const int* src = ei;
    const int* dst = ei + n_edges;

    float *mean, *h;
    int *deg, *rowptr, *cursor, *csr, *bsums, *boffs;
    cudaGetSymbolAddress((void**)&mean,   g_mean);
    cudaGetSymbolAddress((void**)&h,      g_h);
    cudaGetSymbolAddress((void**)&deg,    g_deg);
    cudaGetSymbolAddress((void**)&rowptr, g_rowptr);
    cudaGetSymbolAddress((void**)&cursor, g_cursor);
    cudaGetSymbolAddress((void**)&csr,    g_csrsrc);
    cudaGetSymbolAddress((void**)&bsums,  g_blocksums);
    cudaGetSymbolAddress((void**)&boffs,  g_blockoffs);

    const int SMEM = (2 * D * D + 2 * D * RS) * (int)sizeof(float); // ~98.8 KB
    cudaFuncSetAttribute(combine_kernel,
                         cudaFuncAttributeMaxDynamicSharedMemorySize, SMEM);

    int eblocks = (n_edges + 255) / 256;
    int nscan = (n_nodes + 1023) / 1024;
    int nblocks = (n_nodes + 255) / 256;
    int ablocks = (n_nodes * 32 + 255) / 256;
    int cblocks = (n_nodes + TILE - 1) / TILE;

    // ---- CSR build (once per call) ----
    cudaMemsetAsync(deg, 0, (size_t)n_nodes * sizeof(int));
    count_kernel<<<eblocks, 256>>>(dst, deg, n_edges);
    scan_kernel<<<nscan, 1024>>>(deg, rowptr, bsums, n_nodes);
    scan_kernel<<<1, 1024>>>(bsums, boffs, nullptr, nscan);
    add_off_kernel<<<nblocks, 256>>>(rowptr, cursor, boffs, n_nodes);
    fill_kernel<<<eblocks, 256>>>(src, dst, cursor, csr, n_edges);

    // ---- Layer 1 ----
    aggregate_kernel<<<ablocks, 256>>>((const float2*)x, csr, rowptr, deg,
                                       (float2*)mean, n_nodes);
    combine_kernel<<<cblocks, 128, SMEM>>>(x, mean, W1l, b1l, W1r, h,
                                           n_nodes, 1);

    // ---- Layer 2 ----
    aggregate_kernel<<<ablocks, 256>>>((const float2*)h, csr, rowptr, deg,
                                       (float2*)mean, n_nodes);
    combine_kernel<<<cblocks, 128, SMEM>>>(h, mean, W2l, b2l, W2r, out,
                                           n_nodes, 0);
}

// round 5
// speedup vs baseline: 1.7795x; 1.1439x over previous
#include <cuda_runtime.h>

#define D 64
#define MAXN 100000
#define MAXE 1600000
#define TILE 128

typedef unsigned long long u64;

// ---------------- static scratch (no allocation allowed) -------------------
__device__ float g_mean[(size_t)MAXN * D];
__device__ float g_h[(size_t)MAXN * D];
__device__ int   g_deg[MAXN];
__device__ int   g_rowptr[MAXN];
__device__ int   g_cursor[MAXN];
__device__ int   g_csrsrc[MAXE];
__device__ int   g_blocksums[128];
__device__ int   g_blockoffs[128];

// ---------------- f32x2 helpers --------------------------------------------
__device__ __forceinline__ u64 fma2(u64 a, u64 b, u64 c) {
    u64 d;
    asm("fma.rn.f32x2 %0, %1, %2, %3;" : "=l"(d) : "l"(a), "l"(b), "l"(c));
    return d;
}
__device__ __forceinline__ u64 pack2(float v) {
    u64 d;
    asm("mov.b64 %0, {%1, %1};" : "=l"(d) : "f"(v));
    return d;
}
__device__ __forceinline__ void unpack2(u64 v, float& lo, float& hi) {
    asm("mov.b64 {%0, %1}, %2;" : "=f"(lo), "=f"(hi) : "l"(v));
}

// ---------------- CSR build ------------------------------------------------
__global__ void count_kernel(const int* __restrict__ dst, int* __restrict__ deg,
                             int n_edges) {
    int e = blockIdx.x * blockDim.x + threadIdx.x;
    if (e < n_edges) atomicAdd(deg + __ldg(dst + e), 1);
}

__global__ void scan_kernel(const int* __restrict__ in, int* __restrict__ out,
                            int* sums, int n) {
    __shared__ int sm[1024];
    int t = threadIdx.x;
    int i = blockIdx.x * 1024 + t;
    int v = (i < n) ? in[i] : 0;
    sm[t] = v;
    __syncthreads();
#pragma unroll
    for (int off = 1; off < 1024; off <<= 1) {
        int add = (t >= off) ? sm[t - off] : 0;
        __syncthreads();
        sm[t] += add;
        __syncthreads();
    }
    if (i < n) out[i] = sm[t] - v;            // exclusive
    if (sums != nullptr && t == 1023) sums[blockIdx.x] = sm[1023];
}

__global__ void add_off_kernel(int* __restrict__ rowptr, int* __restrict__ cursor,
                               const int* __restrict__ boffs, int n) {
    int i = blockIdx.x * blockDim.x + threadIdx.x;
    if (i < n) {
        int v = rowptr[i] + boffs[i >> 10];
        rowptr[i] = v;
        cursor[i] = v;
    }
}

__global__ void fill_kernel(const int* __restrict__ src, const int* __restrict__ dst,
                            int* __restrict__ cursor, int* __restrict__ csr,
                            int n_edges) {
    int e = blockIdx.x * blockDim.x + threadIdx.x;
    if (e < n_edges) {
        int d = __ldg(dst + e);
        int pos = atomicAdd(cursor + d, 1);
        csr[pos] = __ldg(src + e);
    }
}

// ---------------- aggregate: mean of in-neighbors ---------------------------
// 2 nodes per warp: lanes 0-15 handle node 2w (16 x float4 = full 256B row),
// lanes 16-31 handle node 2w+1. Unroll 4 -> 4 LDG.128 (2KB) in flight.
__global__ void aggregate_kernel(const float4* __restrict__ x4,
                                 const int* __restrict__ csr,
                                 const int* __restrict__ rowptr,
                                 const int* __restrict__ deg,
                                 float4* __restrict__ mean4, int n_nodes) {
    int warp = (blockIdx.x * blockDim.x + threadIdx.x) >> 5;
    int n0 = warp * 2;
    if (n0 >= n_nodes) return;
    int lane = threadIdx.x & 31;
    int half = lane >> 4;
    int q = lane & 15;
    int node = n0 + half;
    bool valid = node < n_nodes;

    int base = valid ? __ldg(rowptr + node) : 0;
    int dg   = valid ? __ldg(deg + node) : 0;
    int dgA = __shfl_sync(0xffffffffu, dg, 0);
    int dgB = __shfl_sync(0xffffffffu, dg, 16);
    int maxdg = max(dgA, dgB);

    float4 a0 = {0.f,0.f,0.f,0.f}, a1 = {0.f,0.f,0.f,0.f};
    float4 a2 = {0.f,0.f,0.f,0.f}, a3 = {0.f,0.f,0.f,0.f};

    int j = 0;
    for (; j + 4 <= maxdg; j += 4) {
        if (j + 0 < dg) {
            int s = __ldg(csr + base + j + 0);
            float4 v = __ldg(x4 + (size_t)s * 16 + q);
            a0.x += v.x; a0.y += v.y; a0.z += v.z; a0.w += v.w;
        }
        if (j + 1 < dg) {
            int s = __ldg(csr + base + j + 1);
            float4 v = __ldg(x4 + (size_t)s * 16 + q);
            a1.x += v.x; a1.y += v.y; a1.z += v.z; a1.w += v.w;
        }
        if (j + 2 < dg) {
            int s = __ldg(csr + base + j + 2);
            float4 v = __ldg(x4 + (size_t)s * 16 + q);
            a2.x += v.x; a2.y += v.y; a2.z += v.z; a2.w += v.w;
        }
        if (j + 3 < dg) {
            int s = __ldg(csr + base + j + 3);
            float4 v = __ldg(x4 + (size_t)s * 16 + q);
            a3.x += v.x; a3.y += v.y; a3.z += v.z; a3.w += v.w;
        }
    }
    for (; j < maxdg; j++) {
        if (j < dg) {
            int s = __ldg(csr + base + j);
            float4 v = __ldg(x4 + (size_t)s * 16 + q);
            a0.x += v.x; a0.y += v.y; a0.z += v.z; a0.w += v.w;
        }
    }

    float4 a;
    a.x = (a0.x + a1.x) + (a2.x + a3.x);
    a.y = (a0.y + a1.y) + (a2.y + a3.y);
    a.z = (a0.z + a1.z) + (a2.z + a3.z);
    a.w = (a0.w + a1.w) + (a2.w + a3.w);
    float inv = 1.0f / fmaxf((float)dg, 1.0f);
    a.x *= inv; a.y *= inv; a.z *= inv; a.w *= inv;
    if (valid) mean4[(size_t)node * 16 + q] = a;
}

// ---------------- combine (R2 version): out = mean@Wl^T + b + x@Wr^T -------
__global__ void combine_kernel(const float* __restrict__ xin,
                               const float* __restrict__ mean,
                               const float* __restrict__ Wl,
                               const float* __restrict__ bl,
                               const float* __restrict__ Wr,
                               float* __restrict__ out,
                               int n_nodes, int do_relu) {
    extern __shared__ float sm[];
    float* wlT = sm;                 // [64][64] wlT[k*64+f]
    float* wrT = wlT + D * D;
    float* xsT = wrT + D * D;        // [64][128] k-major
    float* msT = xsT + D * TILE;

    int tid = threadIdx.x;
    for (int i = tid; i < D * D; i += 256) {
        int f = i >> 6, k = i & 63;
        wlT[k * D + f] = Wl[i];
        wrT[k * D + f] = Wr[i];
    }
    int nb = blockIdx.x * TILE;
    for (int i = tid; i < TILE * 16; i += 256) {
        int n = i & (TILE - 1);
        int k4 = (i >> 7) * 4;
        int gn = nb + n;
        float4 xv = make_float4(0.f, 0.f, 0.f, 0.f);
        float4 mv = make_float4(0.f, 0.f, 0.f, 0.f);
        if (gn < n_nodes) {
            xv = __ldg((const float4*)(xin + (size_t)gn * D + k4));
            mv = __ldg((const float4*)(mean + (size_t)gn * D + k4));
        }
        xsT[(k4 + 0) * TILE + n] = xv.x;
        xsT[(k4 + 1) * TILE + n] = xv.y;
        xsT[(k4 + 2) * TILE + n] = xv.z;
        xsT[(k4 + 3) * TILE + n] = xv.w;
        msT[(k4 + 0) * TILE + n] = mv.x;
        msT[(k4 + 1) * TILE + n] = mv.y;
        msT[(k4 + 2) * TILE + n] = mv.z;
        msT[(k4 + 3) * TILE + n] = mv.w;
    }
    __syncthreads();

    int fq = tid & 15;
    int g = tid >> 4;

    float4 b4 = __ldg((const float4*)(bl + fq * 4));
    u64 acc[4][4];
    {
        u64 bp0 = pack2(b4.x), bp1 = pack2(b4.y), bp2 = pack2(b4.z), bp3 = pack2(b4.w);
#pragma unroll
        for (int p = 0; p < 4; p++) {
            acc[p][0] = bp0; acc[p][1] = bp1; acc[p][2] = bp2; acc[p][3] = bp3;
        }
    }

    const float4* wl4 = (const float4*)wlT;
    const float4* wr4 = (const float4*)wrT;
    const ulonglong2* msv = (const ulonglong2*)msT;
    const ulonglong2* xsv = (const ulonglong2*)xsT;

#pragma unroll 4
    for (int k = 0; k < D; k++) {
        float4 wl = wl4[k * 16 + fq];
        float4 wr = wr4[k * 16 + fq];
        u64 wl2[4] = {pack2(wl.x), pack2(wl.y), pack2(wl.z), pack2(wl.w)};
        u64 wr2[4] = {pack2(wr.x), pack2(wr.y), pack2(wr.z), pack2(wr.w)};
        ulonglong2 m01 = msv[k * 32 + g];
        ulonglong2 m23 = msv[k * 32 + 16 + g];
        ulonglong2 x01 = xsv[k * 32 + g];
        ulonglong2 x23 = xsv[k * 32 + 16 + g];
#pragma unroll
        for (int f = 0; f < 4; f++) {
            acc[0][f] = fma2(m01.x, wl2[f], acc[0][f]);
            acc[0][f] = fma2(x01.x, wr2[f], acc[0][f]);
            acc[1][f] = fma2(m01.y, wl2[f], acc[1][f]);
            acc[1][f] = fma2(x01.y, wr2[f], acc[1][f]);
            acc[2][f] = fma2(m23.x, wl2[f], acc[2][f]);
            acc[2][f] = fma2(x23.x, wr2[f], acc[2][f]);
            acc[3][f] = fma2(m23.y, wl2[f], acc[3][f]);
            acc[3][f] = fma2(x23.y, wr2[f], acc[3][f]);
        }
    }

#pragma unroll
    for (int p = 0; p < 4; p++) {
        int nlo = (p < 2) ? (4 * g + 2 * p) : (64 + 4 * g + 2 * (p - 2));
        float lo[4], hi[4];
#pragma unroll
        for (int f = 0; f < 4; f++) unpack2(acc[p][f], lo[f], hi[f]);
        if (do_relu) {
#pragma unroll
            for (int f = 0; f < 4; f++) {
                lo[f] = fmaxf(lo[f], 0.f);
                hi[f] = fmaxf(hi[f], 0.f);
            }
        }
        int gn0 = nb + nlo;
        int gn1 = gn0 + 1;
        if (gn0 < n_nodes)
            *(float4*)(out + (size_t)gn0 * D + fq * 4) =
                make_float4(lo[0], lo[1], lo[2], lo[3]);
        if (gn1 < n_nodes)
            *(float4*)(out + (size_t)gn1 * D + fq * 4) =
                make_float4(hi[0], hi[1], hi[2], hi[3]);
    }
}

// ---------------------------------------------------------------------------
extern "C" void kernel_launch(void* const* d_in, const int* in_sizes, int n_in,
                              void* d_out, int out_size) {
    const float* x   = (const float*)d_in[0];
    const int*   ei  = (const int*)  d_in[1];
    const float* W1l = (const float*)d_in[2];
    const float* b1l = (const float*)d_in[3];
    const float* W1r = (const float*)d_in[4];
    const float* W2l = (const float*)d_in[5];
    const float* b2l = (const float*)d_in[6];
    const float* W2r = (const float*)d_in[7];
    float* out = (float*)d_out;

    int n_nodes = in_sizes[0] / D;
    int n_edges = in_sizes[1] / 2;
    const int* src = ei;
    const int* dst = ei + n_edges;

    float *mean, *h;
    int *deg, *rowptr, *cursor, *csr, *bsums, *boffs;
    cudaGetSymbolAddress((void**)&mean,   g_mean);
    cudaGetSymbolAddress((void**)&h,      g_h);
    cudaGetSymbolAddress((void**)&deg,    g_deg);
    cudaGetSymbolAddress((void**)&rowptr, g_rowptr);
    cudaGetSymbolAddress((void**)&cursor, g_cursor);
    cudaGetSymbolAddress((void**)&csr,    g_csrsrc);
    cudaGetSymbolAddress((void**)&bsums,  g_blocksums);
    cudaGetSymbolAddress((void**)&boffs,  g_blockoffs);

    const int SMEM = (2 * D * D + 2 * D * TILE) * (int)sizeof(float); // 96 KB
    cudaFuncSetAttribute(combine_kernel,
                         cudaFuncAttributeMaxDynamicSharedMemorySize, SMEM);

    int eblocks = (n_edges + 255) / 256;
    int nscan = (n_nodes + 1023) / 1024;
    int nblocks = (n_nodes + 255) / 256;
    int npairs = (n_nodes + 1) / 2;
    int ablocks = (npairs * 32 + 255) / 256;
    int cblocks = (n_nodes + TILE - 1) / TILE;

    // ---- CSR build (once per call) ----
    cudaMemsetAsync(deg, 0, (size_t)n_nodes * sizeof(int));
    count_kernel<<<eblocks, 256>>>(dst, deg, n_edges);
    scan_kernel<<<nscan, 1024>>>(deg, rowptr, bsums, n_nodes);
    scan_kernel<<<1, 1024>>>(bsums, boffs, nullptr, nscan);
    add_off_kernel<<<nblocks, 256>>>(rowptr, cursor, boffs, n_nodes);
    fill_kernel<<<eblocks, 256>>>(src, dst, cursor, csr, n_edges);

    // ---- Layer 1 ----
    aggregate_kernel<<<ablocks, 256>>>((const float4*)x, csr, rowptr, deg,
                                       (float4*)mean, n_nodes);
    combine_kernel<<<cblocks, 256, SMEM>>>(x, mean, W1l, b1l, W1r, h,
                                           n_nodes, 1);

    // ---- Layer 2 ----
    aggregate_kernel<<<ablocks, 256>>>((const float4*)h, csr, rowptr, deg,
                                       (float4*)mean, n_nodes);
    combine_kernel<<<cblocks, 256, SMEM>>>(h, mean, W2l, b2l, W2r, out,
                                           n_nodes, 0);
}

// round 6
// speedup vs baseline: 1.8574x; 1.0438x over previous
#include <cuda_runtime.h>
#include <cuda_fp16.h>

#define D 64
#define MAXN 100000
#define MAXE 1600000
#define TILE 128

typedef unsigned long long u64;

// ---------------- static scratch (no allocation allowed) -------------------
__device__ float  g_mean[(size_t)MAXN * D];
__device__ float  g_h[(size_t)MAXN * D];
__device__ __half g_xh[(size_t)MAXN * D];   // fp16 copy of gather operand
__device__ int    g_deg[MAXN];
__device__ int    g_rowptr[MAXN];
__device__ int    g_cursor[MAXN];
__device__ int    g_csrsrc[MAXE];
__device__ int    g_blocksums[128];
__device__ int    g_blockoffs[128];

// ---------------- f32x2 helpers --------------------------------------------
__device__ __forceinline__ u64 fma2(u64 a, u64 b, u64 c) {
    u64 d;
    asm("fma.rn.f32x2 %0, %1, %2, %3;" : "=l"(d) : "l"(a), "l"(b), "l"(c));
    return d;
}
__device__ __forceinline__ u64 pack2(float v) {
    u64 d;
    asm("mov.b64 %0, {%1, %1};" : "=l"(d) : "f"(v));
    return d;
}
__device__ __forceinline__ void unpack2(u64 v, float& lo, float& hi) {
    asm("mov.b64 {%0, %1}, %2;" : "=f"(lo), "=f"(hi) : "l"(v));
}

// ---------------- CSR build ------------------------------------------------
__global__ void count_kernel(const int* __restrict__ dst, int* __restrict__ deg,
                             int n_edges) {
    int e = blockIdx.x * blockDim.x + threadIdx.x;
    if (e < n_edges) atomicAdd(deg + __ldg(dst + e), 1);
}

__global__ void scan_kernel(const int* __restrict__ in, int* __restrict__ out,
                            int* sums, int n) {
    __shared__ int sm[1024];
    int t = threadIdx.x;
    int i = blockIdx.x * 1024 + t;
    int v = (i < n) ? in[i] : 0;
    sm[t] = v;
    __syncthreads();
#pragma unroll
    for (int off = 1; off < 1024; off <<= 1) {
        int add = (t >= off) ? sm[t - off] : 0;
        __syncthreads();
        sm[t] += add;
        __syncthreads();
    }
    if (i < n) out[i] = sm[t] - v;            // exclusive
    if (sums != nullptr && t == 1023) sums[blockIdx.x] = sm[1023];
}

__global__ void add_off_kernel(int* __restrict__ rowptr, int* __restrict__ cursor,
                               const int* __restrict__ boffs, int n) {
    int i = blockIdx.x * blockDim.x + threadIdx.x;
    if (i < n) {
        int v = rowptr[i] + boffs[i >> 10];
        rowptr[i] = v;
        cursor[i] = v;
    }
}

__global__ void fill_kernel(const int* __restrict__ src, const int* __restrict__ dst,
                            int* __restrict__ cursor, int* __restrict__ csr,
                            int n_edges) {
    int e = blockIdx.x * blockDim.x + threadIdx.x;
    if (e < n_edges) {
        int d = __ldg(dst + e);
        int pos = atomicAdd(cursor + d, 1);
        csr[pos] = __ldg(src + e);
    }
}

// ---------------- fp32 -> fp16 conversion (x only) --------------------------
__global__ void convert_kernel(const float4* __restrict__ in,
                               uint2* __restrict__ outh, int n4) {
    int i = blockIdx.x * blockDim.x + threadIdx.x;
    if (i < n4) {
        float4 v = __ldg(in + i);
        __half2 h0 = __floats2half2_rn(v.x, v.y);
        __half2 h1 = __floats2half2_rn(v.z, v.w);
        uint2 o;
        o.x = *(unsigned*)&h0;
        o.y = *(unsigned*)&h1;
        outh[i] = o;
    }
}

// ---------------- aggregate: mean of in-neighbors (fp16 gather) -------------
// 2 nodes/warp: lanes 0-15 node 2w, lanes 16-31 node 2w+1.
// Row = 64 halves = 128B = one cache line (16 lanes x LDG.64). Unroll 8.
__global__ void aggregate_kernel(const uint2* __restrict__ xh2,
                                 const int* __restrict__ csr,
                                 const int* __restrict__ rowptr,
                                 const int* __restrict__ deg,
                                 float4* __restrict__ mean4, int n_nodes) {
    int warp = (blockIdx.x * blockDim.x + threadIdx.x) >> 5;
    int n0 = warp * 2;
    if (n0 >= n_nodes) return;
    int lane = threadIdx.x & 31;
    int half = lane >> 4;
    int q = lane & 15;                 // halves 4q..4q+3 of the row
    int node = n0 + half;
    bool valid = node < n_nodes;

    int base = valid ? __ldg(rowptr + node) : 0;
    int dg   = valid ? __ldg(deg + node) : 0;
    int dgA = __shfl_sync(0xffffffffu, dg, 0);
    int dgB = __shfl_sync(0xffffffffu, dg, 16);
    int maxdg = max(dgA, dgB);

    float a0 = 0.f, a1 = 0.f, a2 = 0.f, a3 = 0.f;

    int j = 0;
    for (; j + 8 <= maxdg; j += 8) {
#pragma unroll
        for (int i = 0; i < 8; i++) {
            if (j + i < dg) {
                int s = __ldg(csr + base + j + i);
                uint2 v = __ldg(xh2 + (size_t)s * 16 + q);
                float2 f0 = __half22float2(*(__half2*)&v.x);
                float2 f1 = __half22float2(*(__half2*)&v.y);
                a0 += f0.x; a1 += f0.y; a2 += f1.x; a3 += f1.y;
            }
        }
    }
    for (; j < maxdg; j++) {
        if (j < dg) {
            int s = __ldg(csr + base + j);
            uint2 v = __ldg(xh2 + (size_t)s * 16 + q);
            float2 f0 = __half22float2(*(__half2*)&v.x);
            float2 f1 = __half22float2(*(__half2*)&v.y);
            a0 += f0.x; a1 += f0.y; a2 += f1.x; a3 += f1.y;
        }
    }

    float inv = 1.0f / fmaxf((float)dg, 1.0f);
    if (valid)
        mean4[(size_t)node * 16 + q] =
            make_float4(a0 * inv, a1 * inv, a2 * inv, a3 * inv);
}

// ---------------- combine: out = mean@Wl^T + b + x@Wr^T (+ReLU) ------------
// Optionally also emits fp16 copy of the output (for next layer's gather).
__global__ void combine_kernel(const float* __restrict__ xin,
                               const float* __restrict__ mean,
                               const float* __restrict__ Wl,
                               const float* __restrict__ bl,
                               const float* __restrict__ Wr,
                               float* __restrict__ out,
                               __half* __restrict__ out_h,
                               int n_nodes, int do_relu) {
    extern __shared__ float sm[];
    float* wlT = sm;                 // [64][64] wlT[k*64+f]
    float* wrT = wlT + D * D;
    float* xsT = wrT + D * D;        // [64][128] k-major
    float* msT = xsT + D * TILE;

    int tid = threadIdx.x;
    for (int i = tid; i < D * D; i += 256) {
        int f = i >> 6, k = i & 63;
        wlT[k * D + f] = Wl[i];
        wrT[k * D + f] = Wr[i];
    }
    int nb = blockIdx.x * TILE;
    for (int i = tid; i < TILE * 16; i += 256) {
        int n = i & (TILE - 1);
        int k4 = (i >> 7) * 4;
        int gn = nb + n;
        float4 xv = make_float4(0.f, 0.f, 0.f, 0.f);
        float4 mv = make_float4(0.f, 0.f, 0.f, 0.f);
        if (gn < n_nodes) {
            xv = __ldg((const float4*)(xin + (size_t)gn * D + k4));
            mv = __ldg((const float4*)(mean + (size_t)gn * D + k4));
        }
        xsT[(k4 + 0) * TILE + n] = xv.x;
        xsT[(k4 + 1) * TILE + n] = xv.y;
        xsT[(k4 + 2) * TILE + n] = xv.z;
        xsT[(k4 + 3) * TILE + n] = xv.w;
        msT[(k4 + 0) * TILE + n] = mv.x;
        msT[(k4 + 1) * TILE + n] = mv.y;
        msT[(k4 + 2) * TILE + n] = mv.z;
        msT[(k4 + 3) * TILE + n] = mv.w;
    }
    __syncthreads();

    int fq = tid & 15;
    int g = tid >> 4;

    float4 b4 = __ldg((const float4*)(bl + fq * 4));
    u64 acc[4][4];
    {
        u64 bp0 = pack2(b4.x), bp1 = pack2(b4.y), bp2 = pack2(b4.z), bp3 = pack2(b4.w);
#pragma unroll
        for (int p = 0; p < 4; p++) {
            acc[p][0] = bp0; acc[p][1] = bp1; acc[p][2] = bp2; acc[p][3] = bp3;
        }
    }

    const float4* wl4 = (const float4*)wlT;
    const float4* wr4 = (const float4*)wrT;
    const ulonglong2* msv = (const ulonglong2*)msT;
    const ulonglong2* xsv = (const ulonglong2*)xsT;

#pragma unroll 4
    for (int k = 0; k < D; k++) {
        float4 wl = wl4[k * 16 + fq];
        float4 wr = wr4[k * 16 + fq];
        u64 wl2[4] = {pack2(wl.x), pack2(wl.y), pack2(wl.z), pack2(wl.w)};
        u64 wr2[4] = {pack2(wr.x), pack2(wr.y), pack2(wr.z), pack2(wr.w)};
        ulonglong2 m01 = msv[k * 32 + g];
        ulonglong2 m23 = msv[k * 32 + 16 + g];
        ulonglong2 x01 = xsv[k * 32 + g];
        ulonglong2 x23 = xsv[k * 32 + 16 + g];
#pragma unroll
        for (int f = 0; f < 4; f++) {
            acc[0][f] = fma2(m01.x, wl2[f], acc[0][f]);
            acc[0][f] = fma2(x01.x, wr2[f], acc[0][f]);
            acc[1][f] = fma2(m01.y, wl2[f], acc[1][f]);
            acc[1][f] = fma2(x01.y, wr2[f], acc[1][f]);
            acc[2][f] = fma2(m23.x, wl2[f], acc[2][f]);
            acc[2][f] = fma2(x23.x, wr2[f], acc[2][f]);
            acc[3][f] = fma2(m23.y, wl2[f], acc[3][f]);
            acc[3][f] = fma2(x23.y, wr2[f], acc[3][f]);
        }
    }

#pragma unroll
    for (int p = 0; p < 4; p++) {
        int nlo = (p < 2) ? (4 * g + 2 * p) : (64 + 4 * g + 2 * (p - 2));
        float lo[4], hi[4];
#pragma unroll
        for (int f = 0; f < 4; f++) unpack2(acc[p][f], lo[f], hi[f]);
        if (do_relu) {
#pragma unroll
            for (int f = 0; f < 4; f++) {
                lo[f] = fmaxf(lo[f], 0.f);
                hi[f] = fmaxf(hi[f], 0.f);
            }
        }
        int gn0 = nb + nlo;
        int gn1 = gn0 + 1;
        if (gn0 < n_nodes) {
            *(float4*)(out + (size_t)gn0 * D + fq * 4) =
                make_float4(lo[0], lo[1], lo[2], lo[3]);
            if (out_h) {
                __half2 h0 = __floats2half2_rn(lo[0], lo[1]);
                __half2 h1 = __floats2half2_rn(lo[2], lo[3]);
                uint2 o;
                o.x = *(unsigned*)&h0;
                o.y = *(unsigned*)&h1;
                *(uint2*)(out_h + (size_t)gn0 * D + fq * 4) = o;
            }
        }
        if (gn1 < n_nodes) {
            *(float4*)(out + (size_t)gn1 * D + fq * 4) =
                make_float4(hi[0], hi[1], hi[2], hi[3]);
            if (out_h) {
                __half2 h0 = __floats2half2_rn(hi[0], hi[1]);
                __half2 h1 = __floats2half2_rn(hi[2], hi[3]);
                uint2 o;
                o.x = *(unsigned*)&h0;
                o.y = *(unsigned*)&h1;
                *(uint2*)(out_h + (size_t)gn1 * D + fq * 4) = o;
            }
        }
    }
}

// ---------------------------------------------------------------------------
extern "C" void kernel_launch(void* const* d_in, const int* in_sizes, int n_in,
                              void* d_out, int out_size) {
    const float* x   = (const float*)d_in[0];
    const int*   ei  = (const int*)  d_in[1];
    const float* W1l = (const float*)d_in[2];
    const float* b1l = (const float*)d_in[3];
    const float* W1r = (const float*)d_in[4];
    const float* W2l = (const float*)d_in[5];
    const float* b2l = (const float*)d_in[6];
    const float* W2r = (const float*)d_in[7];
    float* out = (float*)d_out;

    int n_nodes = in_sizes[0] / D;
    int n_edges = in_sizes[1] / 2;
    const int* src = ei;
    const int* dst = ei + n_edges;

    float *mean, *h;
    __half* xh;
    int *deg, *rowptr, *cursor, *csr, *bsums, *boffs;
    cudaGetSymbolAddress((void**)&mean,   g_mean);
    cudaGetSymbolAddress((void**)&h,      g_h);
    cudaGetSymbolAddress((void**)&xh,     g_xh);
    cudaGetSymbolAddress((void**)&deg,    g_deg);
    cudaGetSymbolAddress((void**)&rowptr, g_rowptr);
    cudaGetSymbolAddress((void**)&cursor, g_cursor);
    cudaGetSymbolAddress((void**)&csr,    g_csrsrc);
    cudaGetSymbolAddress((void**)&bsums,  g_blocksums);
    cudaGetSymbolAddress((void**)&boffs,  g_blockoffs);

    const int SMEM = (2 * D * D + 2 * D * TILE) * (int)sizeof(float); // 96 KB
    cudaFuncSetAttribute(combine_kernel,
                         cudaFuncAttributeMaxDynamicSharedMemorySize, SMEM);

    int eblocks = (n_edges + 255) / 256;
    int nscan = (n_nodes + 1023) / 1024;
    int nblocks = (n_nodes + 255) / 256;
    int npairs = (n_nodes + 1) / 2;
    int ablocks = (npairs * 32 + 255) / 256;
    int cblocks = (n_nodes + TILE - 1) / TILE;
    int n4 = n_nodes * D / 4;
    int vblocks = (n4 + 255) / 256;

    // ---- CSR build + x fp16 conversion (independent; same stream) ----
    cudaMemsetAsync(deg, 0, (size_t)n_nodes * sizeof(int));
    convert_kernel<<<vblocks, 256>>>((const float4*)x, (uint2*)xh, n4);
    count_kernel<<<eblocks, 256>>>(dst, deg, n_edges);
    scan_kernel<<<nscan, 1024>>>(deg, rowptr, bsums, n_nodes);
    scan_kernel<<<1, 1024>>>(bsums, boffs, nullptr, nscan);
    add_off_kernel<<<nblocks, 256>>>(rowptr, cursor, boffs, n_nodes);
    fill_kernel<<<eblocks, 256>>>(src, dst, cursor, csr, n_edges);

    // ---- Layer 1 ----
    aggregate_kernel<<<ablocks, 256>>>((const uint2*)xh, csr, rowptr, deg,
                                       (float4*)mean, n_nodes);
    combine_kernel<<<cblocks, 256, SMEM>>>(x, mean, W1l, b1l, W1r, h, xh,
                                           n_nodes, 1);   // xh now holds h16

    // ---- Layer 2 ----
    aggregate_kernel<<<ablocks, 256>>>((const uint2*)xh, csr, rowptr, deg,
                                       (float4*)mean, n_nodes);
    combine_kernel<<<cblocks, 256, SMEM>>>(h, mean, W2l, b2l, W2r, out, nullptr,
                                           n_nodes, 0);
}